// round 12
// baseline (speedup 1.0000x reference)
#include <cuda_runtime.h>
#include <cstdint>
#include <cstddef>

#define BB 256
#define TT 512
#define NN 128
#define GO_IDX 1
#define EOS_IDX 2
#define NEGV -10000.0f
#define FULLM 0xffffffffu
#define GP 36   // padded stride (floats) per 32-float prev-group (144B, 16B-aligned)

__device__ float g_alpha[(size_t)BB * TT * NN];   // alpha_t rows
__device__ float g_mval [(size_t)BB * TT * NN];   // pre-unary max rows
__device__ float g_p    [(size_t)BB * TT * NN];   // log_softmax(unaries), per-CTA prologue
__device__ float g_score[BB];
__device__ int   g_bestTag[BB];

__device__ __forceinline__ int load_len(const void* lp, int b) {
    const int* p32 = (const int*)lp;
    if (p32[1] == 0) return (int)((const long long*)lp)[b];
    return p32[b];
}

// FFMA-pipe exp (~1e-9 rel on [-87,0])
__device__ __forceinline__ float fexp(float x) {
    float t  = fmaf(x, 1.4426950408889634f, 12582912.0f);
    int   ni = __float_as_int(t) - 0x4B400000;
    float n  = t - 12582912.0f;
    float r  = fmaf(n, -0.693359375f, x);
    r        = fmaf(n,  2.12194440e-4f, r);
    float p  = 1.9841270e-4f;
    p = fmaf(p, r, 1.3888889e-3f);
    p = fmaf(p, r, 8.3333333e-3f);
    p = fmaf(p, r, 4.1666667e-2f);
    p = fmaf(p, r, 1.6666667e-1f);
    p = fmaf(p, r, 0.5f);
    p = fmaf(p, r, 1.0f);
    p = fmaf(p, r, 1.0f);
    int e = ni + 127; if (e < 1) e = 1;
    return p * __int_as_float(e << 23);
}

// ---------------------------------------------------------------------------
// Forward kernel with fused log-softmax prologue.
// Prologue: 16 warps x 32 rows each compute p = (u - m) - log(sum) for this
// batch's 512 rows, bitwise-identical to the proven standalone lse kernel
// (same float4 per-lane layout, same xor-butterfly reduction, same fexp/logf).
// Main loop: 512 threads, tid = cur*4 + g, branchless body (all g-lanes
// redundantly load p / store identical results), scalar FADD/FMNMX, trans in
// regs (float4[8]), padded smem alpha double-buffer, 1 barrier/step.
// ---------------------------------------------------------------------------
__global__ __launch_bounds__(512, 2)
void viterbi_forward(const float* __restrict__ unaries,
                     const float* __restrict__ trans,
                     const void*  __restrict__ lengths)
{
    __shared__ float abuf[2][4 * GP];

    const int b    = blockIdx.x;
    const int tid  = threadIdx.x;
    const int cur  = tid >> 2;
    const int g    = tid & 3;          // prev in [g*32, g*32+32)
    const int wid  = tid >> 5;
    const int lane = tid & 31;
    const int L    = load_len(lengths, b);

    // ---- prologue: materialize g_p rows for this batch ----
    {
        const float* ub = unaries + (size_t)b * TT * NN;
        float*       pb = g_p     + (size_t)b * TT * NN;
        #pragma unroll 4
        for (int i = 0; i < 32; ++i) {
            const int t = i * 16 + wid;
            float4 uv = ((const float4*)(ub + (size_t)t * NN))[lane];
            float m = fmaxf(fmaxf(uv.x, uv.y), fmaxf(uv.z, uv.w));
            #pragma unroll
            for (int off = 16; off; off >>= 1)
                m = fmaxf(m, __shfl_xor_sync(FULLM, m, off));
            float s = fexp(uv.x - m) + fexp(uv.y - m) + fexp(uv.z - m) + fexp(uv.w - m);
            #pragma unroll
            for (int off = 16; off; off >>= 1)
                s += __shfl_xor_sync(FULLM, s, off);
            float ls = logf(s);
            float4 p4;
            p4.x = (uv.x - m) - ls;
            p4.y = (uv.y - m) - ls;
            p4.z = (uv.z - m) - ls;
            p4.w = (uv.w - m) - ls;
            ((float4*)(pb + (size_t)t * NN))[lane] = p4;
        }
    }

    // loop-invariant transition scores: 32 floats as 8 float4 (32 regs)
    float4 tr[8];
    #pragma unroll
    for (int j = 0; j < 8; ++j)
        tr[j] = *(const float4*)(trans + cur * NN + g * 32 + j * 4);

    const int wIdx = (cur >> 5) * GP + (cur & 31);
    abuf[0][wIdx] = (cur == GO_IDX) ? 0.0f : NEGV;   // all g write same value

    const float* prow = g_p     + (size_t)b * TT * NN + cur;
    float*       aout = g_alpha + (size_t)b * TT * NN + cur;
    float*       mout = g_mval  + (size_t)b * TT * NN + cur;

    __syncthreads();   // prologue writes + abuf init visible
    float p = __ldg(prow);   // all lanes (broadcast)

    const float NI = __int_as_float(0xff800000);

    for (int t = 0; t < L; ++t) {
        const int tn = (t + 1 < L) ? t + 1 : t;
        float pn = __ldg(prow + (size_t)tn * NN);      // branchless prefetch

        const float* aS = abuf[t & 1] + g * GP;        // bank-disjoint per g

        float w0 = NI, w1 = NI, w2 = NI, w3 = NI;
        #pragma unroll
        for (int j = 0; j < 8; ++j) {
            float4 a = *(const float4*)(aS + j * 4);
            w0 = fmaxf(w0, a.x + tr[j].x);
            w1 = fmaxf(w1, a.y + tr[j].y);
            w2 = fmaxf(w2, a.z + tr[j].z);
            w3 = fmaxf(w3, a.w + tr[j].w);
        }
        float bv = fmaxf(fmaxf(w0, w1), fmaxf(w2, w3));
        bv = fmaxf(bv, __shfl_xor_sync(FULLM, bv, 1));
        bv = fmaxf(bv, __shfl_xor_sync(FULLM, bv, 2));
        // all 4 g-lanes now hold identical bv

        float a = bv + p;                              // exact passing formula
        abuf[(t + 1) & 1][wIdx] = a;                   // same-addr, same-value
        aout[(size_t)t * NN] = a;
        mout[(size_t)t * NN] = bv;

        p = pn;
        __syncthreads();
    }

    // terminal argmax over prev (first-index), warp 0 only
    if (tid < 32) {
        const float* aF = abuf[L & 1];
        float bv = NI; int bi = 0;
        #pragma unroll
        for (int k = 0; k < 4; ++k) {
            int c = tid * 4 + k;
            float v = aF[(c >> 5) * GP + (c & 31)] + __ldg(trans + EOS_IDX * NN + c);
            if (v > bv) { bv = v; bi = c; }            // in-order: first-index ties
        }
        #pragma unroll
        for (int off = 16; off; off >>= 1) {
            float ov = __shfl_xor_sync(FULLM, bv, off);
            int   oi = __shfl_xor_sync(FULLM, bi, off);
            if (ov > bv || (ov == bv && oi < bi)) { bv = ov; bi = oi; }
        }
        if (tid == 0) { g_score[b] = bv; g_bestTag[b] = bi; }
    }
}

// ---------------------------------------------------------------------------
// Backtrace via equality against stored m (proven, ~35us).
// ---------------------------------------------------------------------------
#define BT_SMEM (65536 + 8 * TT * 4)

__global__ __launch_bounds__(256)
void viterbi_backtrace(const float* __restrict__ trans,
                       const void*  __restrict__ lengths,
                       void* __restrict__ outv, int mode)
{
    extern __shared__ char smem[];
    float4* trS  = (float4*)smem;                 // [128][32] float4
    int*    path = (int*)(smem + 65536);          // [8][TT]

    const int tid = threadIdx.x;
    for (int i = tid; i < 128 * 32; i += 256)
        trS[i] = ((const float4*)trans)[i];
    __syncthreads();

    const int w    = tid >> 5;
    const int lane = tid & 31;
    const int b    = blockIdx.x * 8 + w;
    const int L    = load_len(lengths, b);
    int cur = g_bestTag[b];
    int* mypath = path + w * TT;
    if (lane == 0) mypath[L - 1] = cur;

    const float4* arow = (const float4*)(g_alpha + (size_t)b * TT * NN);
    const float4* mrow = (const float4*)(g_mval  + (size_t)b * TT * NN);

    const int t0 = L - 1;
    float4 ab0, ab1, mb0, mb1;
    ab0 = ab1 = mb0 = mb1 = make_float4(0.f, 0.f, 0.f, 0.f);
    if (t0 >= 1) { ab0 = arow[(size_t)(t0 - 1) * 32 + lane]; mb0 = mrow[(size_t)t0 * 32 + lane]; }
    if (t0 >= 2) { ab1 = arow[(size_t)(t0 - 2) * 32 + lane]; mb1 = mrow[(size_t)(t0 - 1) * 32 + lane]; }

    for (int t = t0; t >= 1; --t) {
        const int par = (t0 - t) & 1;
        float4 av = par ? ab1 : ab0;
        float4 mv = par ? mb1 : mb0;
        if (t >= 3) {
            float4 na = arow[(size_t)(t - 3) * 32 + lane];
            float4 nm = mrow[(size_t)(t - 2) * 32 + lane];
            if (par) { ab1 = na; mb1 = nm; } else { ab0 = na; mb0 = nm; }
        }
        const int sl   = cur >> 2;
        const int comp = cur & 3;
        float mc = (comp == 0) ? mv.x : (comp == 1) ? mv.y : (comp == 2) ? mv.z : mv.w;
        float mstar = __shfl_sync(FULLM, mc, sl);

        float4 tv = trS[cur * 32 + lane];
        float v0 = av.x + tv.x, v1 = av.y + tv.y;
        float v2 = av.z + tv.z, v3 = av.w + tv.w;
        bool e0 = (v0 == mstar), e1 = (v1 == mstar);
        bool e2 = (v2 == mstar), e3 = (v3 == mstar);
        unsigned mask = __ballot_sync(FULLM, e0 | e1 | e2 | e3);
        int wl = __ffs(mask) - 1;
        int lj = 3; if (e2) lj = 2; if (e1) lj = 1; if (e0) lj = 0;
        int ljw = __shfl_sync(FULLM, lj, wl);
        cur = wl * 4 + ljw;
        if (lane == 0) mypath[t - 1] = cur;
    }
    __syncwarp();

    float* outf = (float*)outv;
    int*   outi = (int*)outv;
    for (int tt = lane; tt < TT; tt += 32) {
        int v = (tt < L) ? mypath[tt] : 0;
        if (mode) outf[b * TT + tt] = (float)v;
        else      outi[b * TT + tt] = v;
    }
    if (mode && lane == 0) outf[BB * TT + b] = g_score[b];
}

extern "C" void kernel_launch(void* const* d_in, const int* in_sizes, int n_in,
                              void* d_out, int out_size)
{
    const float* unaries = (const float*)d_in[0];
    const float* trans   = (const float*)d_in[1];
    const void*  lengths = d_in[2];

    cudaFuncSetAttribute(viterbi_backtrace,
                         cudaFuncAttributeMaxDynamicSharedMemorySize, BT_SMEM);

    const int mode = (out_size == BB * TT + BB) ? 1 : 0;

    viterbi_forward<<<BB, 512>>>(unaries, trans, lengths);
    viterbi_backtrace<<<32, 256, BT_SMEM>>>(trans, lengths, d_out, mode);
}

// round 14
// speedup vs baseline: 1.4894x; 1.4894x over previous
#include <cuda_runtime.h>
#include <cstdint>
#include <cstddef>

#define BB 256
#define TT 512
#define NN 128
#define GO_IDX 1
#define EOS_IDX 2
#define NEGV -10000.0f
#define FULLM 0xffffffffu
#define GP 36   // padded stride (floats) per 32-float prev-group

__device__ float g_alpha[(size_t)BB * TT * NN];   // alpha_t rows
__device__ float g_mval [(size_t)BB * TT * NN];   // pre-unary max rows
__device__ float g_p    [(size_t)BB * TT * NN];   // precomputed log_softmax(unaries)
__device__ float g_score[BB];
__device__ int   g_bestTag[BB];

__device__ __forceinline__ int load_len(const void* lp, int b) {
    const int* p32 = (const int*)lp;
    if (p32[1] == 0) return (int)((const long long*)lp)[b];
    return p32[b];
}

// FFMA-pipe exp (~1e-9 rel on [-87,0])
__device__ __forceinline__ float fexp(float x) {
    float t  = fmaf(x, 1.4426950408889634f, 12582912.0f);
    int   ni = __float_as_int(t) - 0x4B400000;
    float n  = t - 12582912.0f;
    float r  = fmaf(n, -0.693359375f, x);
    r        = fmaf(n,  2.12194440e-4f, r);
    float p  = 1.9841270e-4f;
    p = fmaf(p, r, 1.3888889e-3f);
    p = fmaf(p, r, 8.3333333e-3f);
    p = fmaf(p, r, 4.1666667e-2f);
    p = fmaf(p, r, 1.6666667e-1f);
    p = fmaf(p, r, 0.5f);
    p = fmaf(p, r, 1.0f);
    p = fmaf(p, r, 1.0f);
    int e = ni + 127; if (e < 1) e = 1;
    return p * __int_as_float(e << 23);
}

// ---------------------------------------------------------------------------
// Kernel 1: per-(b,t) log-softmax, materialized (proven, ~26us).
// ---------------------------------------------------------------------------
__global__ __launch_bounds__(256)
void lse_kernel(const float* __restrict__ unaries)
{
    const int row  = blockIdx.x * 8 + (threadIdx.x >> 5);
    const int lane = threadIdx.x & 31;
    float4 uv = ((const float4*)(unaries + (size_t)row * NN))[lane];
    float m = fmaxf(fmaxf(uv.x, uv.y), fmaxf(uv.z, uv.w));
    #pragma unroll
    for (int off = 16; off; off >>= 1)
        m = fmaxf(m, __shfl_xor_sync(FULLM, m, off));
    float s = fexp(uv.x - m) + fexp(uv.y - m) + fexp(uv.z - m) + fexp(uv.w - m);
    #pragma unroll
    for (int off = 16; off; off >>= 1)
        s += __shfl_xor_sync(FULLM, s, off);
    float ls = logf(s);
    float4 p4;
    p4.x = (uv.x - m) - ls;
    p4.y = (uv.y - m) - ls;
    p4.z = (uv.z - m) - ls;
    p4.w = (uv.w - m) - ls;
    ((float4*)(g_p + (size_t)row * NN))[lane] = p4;
}

// ---------------------------------------------------------------------------
// Kernel 2: forward, pure max (R11, proven ~328us). 512 threads, tid=cur*4+g.
// ---------------------------------------------------------------------------
__global__ __launch_bounds__(512, 2)
void viterbi_forward(const float* __restrict__ trans,
                     const void*  __restrict__ lengths)
{
    __shared__ float abuf[2][4 * GP];

    const int b   = blockIdx.x;
    const int tid = threadIdx.x;
    const int cur = tid >> 2;
    const int g   = tid & 3;          // prev in [g*32, g*32+32)
    const int L   = load_len(lengths, b);

    float4 tr[8];
    #pragma unroll
    for (int j = 0; j < 8; ++j)
        tr[j] = *(const float4*)(trans + cur * NN + g * 32 + j * 4);

    const int wIdx = (cur >> 5) * GP + (cur & 31);
    if (g == 0) abuf[0][wIdx] = (cur == GO_IDX) ? 0.0f : NEGV;

    const float* prow = g_p     + (size_t)b * TT * NN + cur;
    float*       aout = g_alpha + (size_t)b * TT * NN + cur;
    float*       mout = g_mval  + (size_t)b * TT * NN + cur;

    float p = 0.f;
    if (g == 0) p = __ldg(prow);
    __syncthreads();

    const float NI = __int_as_float(0xff800000);

    for (int t = 0; t < L; ++t) {
        float pn = 0.f;
        if (g == 0) {
            int tn = (t + 1 < L) ? t + 1 : t;
            pn = __ldg(prow + (size_t)tn * NN);
        }
        const float* aS = abuf[t & 1] + g * GP;

        float w0 = NI, w1 = NI, w2 = NI, w3 = NI;
        #pragma unroll
        for (int j = 0; j < 8; ++j) {
            float4 a = *(const float4*)(aS + j * 4);
            w0 = fmaxf(w0, a.x + tr[j].x);
            w1 = fmaxf(w1, a.y + tr[j].y);
            w2 = fmaxf(w2, a.z + tr[j].z);
            w3 = fmaxf(w3, a.w + tr[j].w);
        }
        float bv = fmaxf(fmaxf(w0, w1), fmaxf(w2, w3));
        bv = fmaxf(bv, __shfl_xor_sync(FULLM, bv, 1));
        bv = fmaxf(bv, __shfl_xor_sync(FULLM, bv, 2));

        if (g == 0) {
            float a = bv + p;
            abuf[(t + 1) & 1][wIdx] = a;
            aout[(size_t)t * NN] = a;
            mout[(size_t)t * NN] = bv;
        }
        p = pn;
        __syncthreads();
    }

    if (tid < 32) {
        const float* aF = abuf[L & 1];
        float bv = NI; int bi = 0;
        #pragma unroll
        for (int k = 0; k < 4; ++k) {
            int c = tid * 4 + k;
            float v = aF[(c >> 5) * GP + (c & 31)] + __ldg(trans + EOS_IDX * NN + c);
            if (v > bv) { bv = v; bi = c; }
        }
        #pragma unroll
        for (int off = 16; off; off >>= 1) {
            float ov = __shfl_xor_sync(FULLM, bv, off);
            int   oi = __shfl_xor_sync(FULLM, bi, off);
            if (ov > bv || (ov == bv && oi < bi)) { bv = ov; bi = oi; }
        }
        if (tid == 0) { g_score[b] = bv; g_bestTag[b] = bi; }
    }
}

// ---------------------------------------------------------------------------
// Kernel 3: backtrace, chunked depth-8 prefetch + REDUX first-index argmatch.
// All gmem row addresses are cur-independent, so a whole chunk of alpha/m rows
// is loaded one chunk ahead into register arrays (static indices, no spills).
// Per-step serial chain: shfl(mstar) || LDS(trans row) + FADD + FSETP + SELs
// + __reduce_min_sync  (~95 cyc vs ~1100 before).
// ---------------------------------------------------------------------------
#define BT_SMEM (65536 + 8 * TT * 4)

__global__ __launch_bounds__(256)
void viterbi_backtrace(const float* __restrict__ trans,
                       const void*  __restrict__ lengths,
                       void* __restrict__ outv, int mode)
{
    extern __shared__ char smem[];
    float4* trS  = (float4*)smem;                 // [128][32] float4
    int*    path = (int*)(smem + 65536);          // [8][TT]

    const int tid = threadIdx.x;
    for (int i = tid; i < 128 * 32; i += 256)
        trS[i] = ((const float4*)trans)[i];
    __syncthreads();

    const int w    = tid >> 5;
    const int lane = tid & 31;
    const int b    = blockIdx.x * 8 + w;
    const int L    = load_len(lengths, b);
    int cur = g_bestTag[b];
    int* mypath = path + w * TT;
    if (lane == 0) mypath[L - 1] = cur;

    const float4* arow = (const float4*)(g_alpha + (size_t)b * TT * NN);
    const float4* mrow = (const float4*)(g_mval  + (size_t)b * TT * NN);

    // iteration t uses arow[t-1] (alphas) and mrow[t] (max values)
    float4 A[8], M[8], A2[8], M2[8];
    int tc = L - 1;

    #pragma unroll
    for (int k = 0; k < 8; ++k) {
        int ta = tc - 1 - k; if (ta < 0) ta = 0;
        int tm = tc - k;     if (tm < 0) tm = 0;
        A[k] = arow[(size_t)ta * 32 + lane];
        M[k] = mrow[(size_t)tm * 32 + lane];
    }

    while (tc >= 1) {
        const int tn = tc - 8;
        #pragma unroll
        for (int k = 0; k < 8; ++k) {          // prefetch next chunk (clamped)
            int ta = tn - 1 - k; if (ta < 0) ta = 0;
            int tm = tn - k;     if (tm < 0) tm = 0;
            A2[k] = arow[(size_t)ta * 32 + lane];
            M2[k] = mrow[(size_t)tm * 32 + lane];
        }
        #pragma unroll
        for (int k = 0; k < 8; ++k) {
            const int t = tc - k;
            if (t >= 1) {                      // uniform branch
                float4 av = A[k], mv = M[k];
                const int sl   = cur >> 2;
                const int comp = cur & 3;
                float mc = (comp == 0) ? mv.x : (comp == 1) ? mv.y
                         : (comp == 2) ? mv.z : mv.w;
                float mstar = __shfl_sync(FULLM, mc, sl);

                float4 tv = trS[cur * 32 + lane];
                float v0 = av.x + tv.x, v1 = av.y + tv.y;
                float v2 = av.z + tv.z, v3 = av.w + tv.w;
                const int base = lane * 4;
                unsigned cand = 255u;           // priority select: lowest index wins
                if (v3 == mstar) cand = base + 3;
                if (v2 == mstar) cand = base + 2;
                if (v1 == mstar) cand = base + 1;
                if (v0 == mstar) cand = base;
                cur = (int)__reduce_min_sync(FULLM, cand);
                if (lane == 0) mypath[t - 1] = cur;
            }
        }
        #pragma unroll
        for (int k = 0; k < 8; ++k) { A[k] = A2[k]; M[k] = M2[k]; }
        tc -= 8;
    }
    __syncwarp();

    float* outf = (float*)outv;
    int*   outi = (int*)outv;
    for (int tt = lane; tt < TT; tt += 32) {
        int v = (tt < L) ? mypath[tt] : 0;
        if (mode) outf[b * TT + tt] = (float)v;
        else      outi[b * TT + tt] = v;
    }
    if (mode && lane == 0) outf[BB * TT + b] = g_score[b];
}

extern "C" void kernel_launch(void* const* d_in, const int* in_sizes, int n_in,
                              void* d_out, int out_size)
{
    const float* unaries = (const float*)d_in[0];
    const float* trans   = (const float*)d_in[1];
    const void*  lengths = d_in[2];

    cudaFuncSetAttribute(viterbi_backtrace,
                         cudaFuncAttributeMaxDynamicSharedMemorySize, BT_SMEM);

    const int mode = (out_size == BB * TT + BB) ? 1 : 0;

    lse_kernel<<<(BB * TT) / 8, 256>>>(unaries);
    viterbi_forward<<<BB, 512>>>(trans, lengths);
    viterbi_backtrace<<<32, 256, BT_SMEM>>>(trans, lengths, d_out, mode);
}

// round 16
// speedup vs baseline: 1.6730x; 1.1233x over previous
#include <cuda_runtime.h>
#include <cstdint>
#include <cstddef>

#define BB 256
#define TT 512
#define NN 128
#define GO_IDX 1
#define EOS_IDX 2
#define NEGV -10000.0f
#define FULLM 0xffffffffu
#define GP 36   // padded stride (floats) per 32-float prev-group (144B)

__device__ float g_alpha[(size_t)BB * TT * NN];   // alpha_t rows
__device__ float g_mval [(size_t)BB * TT * NN];   // pre-unary max rows
__device__ float g_p    [(size_t)BB * TT * NN];   // precomputed log_softmax(unaries)
__device__ float g_score[BB];
__device__ int   g_bestTag[BB];

__device__ __forceinline__ int load_len(const void* lp, int b) {
    const int* p32 = (const int*)lp;
    if (p32[1] == 0) return (int)((const long long*)lp)[b];
    return p32[b];
}

// packed f32x2 add: two independent rn adds, bitwise == scalar FADD (proven R9)
__device__ __forceinline__ double add2d(double a, double b) {
    double r;
    asm("add.rn.f32x2 %0, %1, %2;" : "=d"(r) : "d"(a), "d"(b));
    return r;
}
// free register aliasing: double -> its two float components
__device__ __forceinline__ float2 lo_hi(double d) {
    return *reinterpret_cast<float2*>(&d);
}

// FFMA-pipe exp (~1e-9 rel on [-87,0])
__device__ __forceinline__ float fexp(float x) {
    float t  = fmaf(x, 1.4426950408889634f, 12582912.0f);
    int   ni = __float_as_int(t) - 0x4B400000;
    float n  = t - 12582912.0f;
    float r  = fmaf(n, -0.693359375f, x);
    r        = fmaf(n,  2.12194440e-4f, r);
    float p  = 1.9841270e-4f;
    p = fmaf(p, r, 1.3888889e-3f);
    p = fmaf(p, r, 8.3333333e-3f);
    p = fmaf(p, r, 4.1666667e-2f);
    p = fmaf(p, r, 1.6666667e-1f);
    p = fmaf(p, r, 0.5f);
    p = fmaf(p, r, 1.0f);
    p = fmaf(p, r, 1.0f);
    int e = ni + 127; if (e < 1) e = 1;
    return p * __int_as_float(e << 23);
}

// ---------------------------------------------------------------------------
// Kernel 1: per-(b,t) log-softmax, materialized (proven, ~25us).
// ---------------------------------------------------------------------------
__global__ __launch_bounds__(256)
void lse_kernel(const float* __restrict__ unaries)
{
    const int row  = blockIdx.x * 8 + (threadIdx.x >> 5);
    const int lane = threadIdx.x & 31;
    float4 uv = ((const float4*)(unaries + (size_t)row * NN))[lane];
    float m = fmaxf(fmaxf(uv.x, uv.y), fmaxf(uv.z, uv.w));
    #pragma unroll
    for (int off = 16; off; off >>= 1)
        m = fmaxf(m, __shfl_xor_sync(FULLM, m, off));
    float s = fexp(uv.x - m) + fexp(uv.y - m) + fexp(uv.z - m) + fexp(uv.w - m);
    #pragma unroll
    for (int off = 16; off; off >>= 1)
        s += __shfl_xor_sync(FULLM, s, off);
    float ls = logf(s);
    float4 p4;
    p4.x = (uv.x - m) - ls;
    p4.y = (uv.y - m) - ls;
    p4.z = (uv.z - m) - ls;
    p4.w = (uv.w - m) - ls;
    ((float4*)(g_p + (size_t)row * NN))[lane] = p4;
}

// ---------------------------------------------------------------------------
// Kernel 2: forward, packed f32x2 adds + scalar FMNMX tree, branchless loop.
// 512 threads, tid = cur*4 + g. Trans in regs as 16 packed pairs (doubles).
// Alphas via LDS.128 reinterpreted to 2 doubles (no repack MOVs). All lanes
// redundantly load p / store identical results -> zero BSSY in the loop.
// ---------------------------------------------------------------------------
__global__ __launch_bounds__(512, 2)
void viterbi_forward(const float* __restrict__ trans,
                     const void*  __restrict__ lengths)
{
    __shared__ __align__(16) float abuf[2][4 * GP];

    const int b   = blockIdx.x;
    const int tid = threadIdx.x;
    const int cur = tid >> 2;
    const int g   = tid & 3;          // prev in [g*32, g*32+32)
    const int L   = load_len(lengths, b);

    // loop-invariant transition scores: 32 floats = 16 packed pairs (32 regs)
    double trD[16];
    #pragma unroll
    for (int j = 0; j < 16; ++j)
        trD[j] = *(const double*)(trans + cur * NN + g * 32 + j * 2);

    const int wIdx = (cur >> 5) * GP + (cur & 31);
    abuf[0][wIdx] = (cur == GO_IDX) ? 0.0f : NEGV;   // all g: same value

    const float* prow = g_p     + (size_t)b * TT * NN + cur;
    float*       aout = g_alpha + (size_t)b * TT * NN + cur;
    float*       mout = g_mval  + (size_t)b * TT * NN + cur;

    __syncthreads();
    float p = __ldg(prow);                            // all lanes (broadcast)

    const float NI = __int_as_float(0xff800000);

    for (int t = 0; t < L; ++t) {
        const int tn = (t + 1 < L) ? t + 1 : t;
        float pn = __ldg(prow + (size_t)tn * NN);     // branchless prefetch

        const float* aS = abuf[t & 1] + g * GP;       // bank-disjoint per g

        float w0 = NI, w1 = NI, w2 = NI, w3 = NI;
        #pragma unroll
        for (int j = 0; j < 8; j += 2) {
            float4 a0 = *(const float4*)(aS + j * 4);
            float4 a1 = *(const float4*)(aS + j * 4 + 4);
            const double* d0 = reinterpret_cast<const double*>(&a0);
            const double* d1 = reinterpret_cast<const double*>(&a1);
            float2 s0 = lo_hi(add2d(d0[0], trD[2 * j]));
            float2 s1 = lo_hi(add2d(d0[1], trD[2 * j + 1]));
            float2 s2 = lo_hi(add2d(d1[0], trD[2 * j + 2]));
            float2 s3 = lo_hi(add2d(d1[1], trD[2 * j + 3]));
            w0 = fmaxf(w0, fmaxf(s0.x, s0.y));
            w1 = fmaxf(w1, fmaxf(s1.x, s1.y));
            w2 = fmaxf(w2, fmaxf(s2.x, s2.y));
            w3 = fmaxf(w3, fmaxf(s3.x, s3.y));
        }
        float bv = fmaxf(fmaxf(w0, w1), fmaxf(w2, w3));
        bv = fmaxf(bv, __shfl_xor_sync(FULLM, bv, 1));
        bv = fmaxf(bv, __shfl_xor_sync(FULLM, bv, 2));
        // all 4 g-lanes hold identical bv

        float a = bv + p;                             // exact passing formula
        abuf[(t + 1) & 1][wIdx] = a;                  // same-addr same-value
        aout[(size_t)t * NN] = a;                     // redundant stores dedup
        mout[(size_t)t * NN] = bv;

        p = pn;
        __syncthreads();
    }

    // terminal argmax over prev (first-index), warp 0 only
    if (tid < 32) {
        const float* aF = abuf[L & 1];
        float bv = NI; int bi = 0;
        #pragma unroll
        for (int k = 0; k < 4; ++k) {
            int c = tid * 4 + k;
            float v = aF[(c >> 5) * GP + (c & 31)] + __ldg(trans + EOS_IDX * NN + c);
            if (v > bv) { bv = v; bi = c; }           // in-order: first-index ties
        }
        #pragma unroll
        for (int off = 16; off; off >>= 1) {
            float ov = __shfl_xor_sync(FULLM, bv, off);
            int   oi = __shfl_xor_sync(FULLM, bi, off);
            if (ov > bv || (ov == bv && oi < bi)) { bv = ov; bi = oi; }
        }
        if (tid == 0) { g_score[b] = bv; g_bestTag[b] = bi; }
    }
}

// ---------------------------------------------------------------------------
// Kernel 3: backtrace, chunked depth-8 prefetch, branchless chunk body:
// full chunks in the main loop (no per-k guard), all-lane path stores,
// scalar tail for the ragged end.
// ---------------------------------------------------------------------------
#define BT_SMEM (65536 + 8 * TT * 4)

__global__ __launch_bounds__(256)
void viterbi_backtrace(const float* __restrict__ trans,
                       const void*  __restrict__ lengths,
                       void* __restrict__ outv, int mode)
{
    extern __shared__ char smem[];
    float4* trS  = (float4*)smem;                 // [128][32] float4
    int*    path = (int*)(smem + 65536);          // [8][TT]

    const int tid = threadIdx.x;
    for (int i = tid; i < 128 * 32; i += 256)
        trS[i] = ((const float4*)trans)[i];
    __syncthreads();

    const int w    = tid >> 5;
    const int lane = tid & 31;
    const int b    = blockIdx.x * 8 + w;
    const int L    = load_len(lengths, b);
    int cur = g_bestTag[b];
    int* mypath = path + w * TT;
    mypath[L - 1] = cur;                          // all lanes, same value

    const float4* arow = (const float4*)(g_alpha + (size_t)b * TT * NN);
    const float4* mrow = (const float4*)(g_mval  + (size_t)b * TT * NN);

    // iteration t uses arow[t-1] and mrow[t]
    float4 A[8], M[8], A2[8], M2[8];
    int tc = L - 1;

    #pragma unroll
    for (int k = 0; k < 8; ++k) {
        int ta = tc - 1 - k; if (ta < 0) ta = 0;
        int tm = tc - k;     if (tm < 0) tm = 0;
        A[k] = arow[(size_t)ta * 32 + lane];
        M[k] = mrow[(size_t)tm * 32 + lane];
    }

    // main loop: only full chunks (t = tc..tc-7 all >= 1) -> branchless body
    while (tc >= 8) {
        const int tn = tc - 8;
        #pragma unroll
        for (int k = 0; k < 8; ++k) {             // prefetch next chunk (clamped)
            int ta = tn - 1 - k; if (ta < 0) ta = 0;
            int tm = tn - k;     if (tm < 0) tm = 0;
            A2[k] = arow[(size_t)ta * 32 + lane];
            M2[k] = mrow[(size_t)tm * 32 + lane];
        }
        #pragma unroll
        for (int k = 0; k < 8; ++k) {
            float4 av = A[k], mv = M[k];
            const int sl   = cur >> 2;
            const int comp = cur & 3;
            float mc = (comp == 0) ? mv.x : (comp == 1) ? mv.y
                     : (comp == 2) ? mv.z : mv.w;
            float mstar = __shfl_sync(FULLM, mc, sl);

            float4 tv = trS[cur * 32 + lane];
            float v0 = av.x + tv.x, v1 = av.y + tv.y;
            float v2 = av.z + tv.z, v3 = av.w + tv.w;
            const int base = lane * 4;
            unsigned cand = 255u;                 // priority: lowest index wins
            if (v3 == mstar) cand = base + 3;
            if (v2 == mstar) cand = base + 2;
            if (v1 == mstar) cand = base + 1;
            if (v0 == mstar) cand = base;
            cur = (int)__reduce_min_sync(FULLM, cand);
            mypath[tc - k - 1] = cur;             // all lanes, same value
        }
        #pragma unroll
        for (int k = 0; k < 8; ++k) { A[k] = A2[k]; M[k] = M2[k]; }
        tc -= 8;
    }

    // scalar tail: t = tc..1 (<= 7 steps), direct loads
    for (int t = tc; t >= 1; --t) {
        float4 av = arow[(size_t)(t - 1) * 32 + lane];
        float4 mv = mrow[(size_t)t * 32 + lane];
        const int sl   = cur >> 2;
        const int comp = cur & 3;
        float mc = (comp == 0) ? mv.x : (comp == 1) ? mv.y
                 : (comp == 2) ? mv.z : mv.w;
        float mstar = __shfl_sync(FULLM, mc, sl);

        float4 tv = trS[cur * 32 + lane];
        float v0 = av.x + tv.x, v1 = av.y + tv.y;
        float v2 = av.z + tv.z, v3 = av.w + tv.w;
        const int base = lane * 4;
        unsigned cand = 255u;
        if (v3 == mstar) cand = base + 3;
        if (v2 == mstar) cand = base + 2;
        if (v1 == mstar) cand = base + 1;
        if (v0 == mstar) cand = base;
        cur = (int)__reduce_min_sync(FULLM, cand);
        mypath[t - 1] = cur;
    }
    __syncwarp();

    float* outf = (float*)outv;
    int*   outi = (int*)outv;
    for (int tt = lane; tt < TT; tt += 32) {
        int v = (tt < L) ? mypath[tt] : 0;
        if (mode) outf[b * TT + tt] = (float)v;
        else      outi[b * TT + tt] = v;
    }
    if (mode && lane == 0) outf[BB * TT + b] = g_score[b];
}

extern "C" void kernel_launch(void* const* d_in, const int* in_sizes, int n_in,
                              void* d_out, int out_size)
{
    const float* unaries = (const float*)d_in[0];
    const float* trans   = (const float*)d_in[1];
    const void*  lengths = d_in[2];

    cudaFuncSetAttribute(viterbi_backtrace,
                         cudaFuncAttributeMaxDynamicSharedMemorySize, BT_SMEM);

    const int mode = (out_size == BB * TT + BB) ? 1 : 0;

    lse_kernel<<<(BB * TT) / 8, 256>>>(unaries);
    viterbi_forward<<<BB, 512>>>(trans, lengths);
    viterbi_backtrace<<<32, 256, BT_SMEM>>>(trans, lengths, d_out, mode);
}